// round 1
// baseline (speedup 1.0000x reference)
#include <cuda_runtime.h>
#include <cuda_bf16.h>
#include <mma.h>
#include <math.h>

using namespace nvcuda;

#define BATCH 8
#define SEQ   1124
#define EMBED 1024
#define NHEAD 16
#define HD    64
#define NQ    100
#define NP    1024
#define MLPH  4096
#define ROWS  (BATCH*SEQ)   // 8992

// ---------------- scratch (static device memory; no allocations allowed) ---------
__device__ float g_xn  [(size_t)ROWS*EMBED];
__device__ float g_qkv [(size_t)ROWS*3*EMBED];
__device__ float g_scor[(size_t)BATCH*NHEAD*SEQ*SEQ];
__device__ float g_att [(size_t)ROWS*EMBED];
__device__ float g_x1  [(size_t)ROWS*EMBED];
__device__ float g_h2  [(size_t)ROWS*EMBED];
__device__ float g_hid [(size_t)ROWS*MLPH];

// ---------------- LayerNorm over last dim (1024), one block per row -------------
__global__ void __launch_bounds__(256) ln_kernel(const float* __restrict__ x,
                                                 const float* __restrict__ g,
                                                 const float* __restrict__ b,
                                                 float* __restrict__ o)
{
    int row = blockIdx.x;
    const float4* xr = (const float4*)(x + (size_t)row*EMBED);
    float4 v = xr[threadIdx.x];
    float s  = v.x + v.y + v.z + v.w;
    float sq = v.x*v.x + v.y*v.y + v.z*v.z + v.w*v.w;

    __shared__ float red[2][8];
    #pragma unroll
    for (int off = 16; off > 0; off >>= 1) {
        s  += __shfl_down_sync(0xffffffffu, s,  off);
        sq += __shfl_down_sync(0xffffffffu, sq, off);
    }
    int w = threadIdx.x >> 5, l = threadIdx.x & 31;
    if (l == 0) { red[0][w] = s; red[1][w] = sq; }
    __syncthreads();
    if (threadIdx.x == 0) {
        float ts = 0.f, tq = 0.f;
        #pragma unroll
        for (int i = 0; i < 8; i++) { ts += red[0][i]; tq += red[1][i]; }
        red[0][0] = ts; red[1][0] = tq;
    }
    __syncthreads();
    float mean = red[0][0] * (1.0f/EMBED);
    float var  = red[1][0] * (1.0f/EMBED) - mean*mean;
    float inv  = rsqrtf(var + 1e-6f);

    int c = threadIdx.x * 4;
    float4 gv = *(const float4*)(g + c);
    float4 bv = *(const float4*)(b + c);
    float4 ov;
    ov.x = (v.x - mean) * inv * gv.x + bv.x;
    ov.y = (v.y - mean) * inv * gv.y + bv.y;
    ov.z = (v.z - mean) * inv * gv.z + bv.z;
    ov.w = (v.w - mean) * inv * gv.w + bv.w;
    ((float4*)(o + (size_t)row*EMBED))[threadIdx.x] = ov;
}

// ---------------- masked softmax over rows of length SEQ ------------------------
// grid: (SEQ, NHEAD, BATCH); block 128.  Row q>=NP gets mask on cols [0,NP).
__global__ void __launch_bounds__(128) softmax_kernel(float* __restrict__ scores,
                                                      const float* __restrict__ mask)
{
    int q = blockIdx.x, h = blockIdx.y, b = blockIdx.z;
    float* row = scores + (((size_t)(b*NHEAD + h))*SEQ + q)*SEQ;
    const float* mrow = (q >= NP) ? (mask + ((size_t)b*NQ + (q - NP))*NP) : nullptr;

    float v[9];
    float mx = -3.0e38f;
    #pragma unroll
    for (int i = 0; i < 9; i++) {
        int c = threadIdx.x + i*128;
        float val = -3.0e38f;
        if (c < SEQ) {
            val = row[c];
            if (mrow && c < NP && !(mrow[c] > 0.5f)) val = -1e9f;
        }
        v[i] = val;
        mx = fmaxf(mx, val);
    }

    __shared__ float red[4];
    #pragma unroll
    for (int off = 16; off > 0; off >>= 1)
        mx = fmaxf(mx, __shfl_down_sync(0xffffffffu, mx, off));
    int w = threadIdx.x >> 5, l = threadIdx.x & 31;
    if (l == 0) red[w] = mx;
    __syncthreads();
    if (threadIdx.x == 0) {
        float m = red[0];
        #pragma unroll
        for (int i = 1; i < 4; i++) m = fmaxf(m, red[i]);
        red[0] = m;
    }
    __syncthreads();
    mx = red[0];
    __syncthreads();

    float s = 0.f;
    #pragma unroll
    for (int i = 0; i < 9; i++) {
        int c = threadIdx.x + i*128;
        if (c < SEQ) { v[i] = expf(v[i] - mx); s += v[i]; }
    }
    #pragma unroll
    for (int off = 16; off > 0; off >>= 1)
        s += __shfl_down_sync(0xffffffffu, s, off);
    if (l == 0) red[w] = s;
    __syncthreads();
    if (threadIdx.x == 0) {
        float t = 0.f;
        #pragma unroll
        for (int i = 0; i < 4; i++) t += red[i];
        red[0] = t;
    }
    __syncthreads();
    float inv = 1.0f / red[0];

    #pragma unroll
    for (int i = 0; i < 9; i++) {
        int c = threadIdx.x + i*128;
        if (c < SEQ) row[c] = v[i] * inv;
    }
}

// ---------------- generic TF32 WMMA GEMM ----------------------------------------
// C[m,n] = sum_k A[m,k] * (BT ? B[n,k] : B[k,n]),  bounds-checked, batched via
// blockIdx.z decomposed as (b,h) with separate strides.  Epilogues templated.
enum { EPI_NONE = 0, EPI_SCALE = 1, EPI_BIAS_RES = 2, EPI_BIAS_GELU = 3 };

template<int EPI, bool BT>
__global__ void __launch_bounds__(256) gemm_kernel(
    int M, int N, int K,
    const float* __restrict__ A, int lda, long long sAb, long long sAh,
    const float* __restrict__ B, int ldb, long long sBb, long long sBh,
    float* __restrict__ C, int ldc, long long sCb, long long sCh,
    const float* __restrict__ bias,
    const float* __restrict__ res, int ldr,
    float scale, int nh)
{
    constexpr int BM = 128, BN = 128, BK = 32;
    __shared__ float As[BM][BK];       // 16 KB
    __shared__ float Bs[BK][BN];       // 16 KB
    __shared__ float stage[8][256];    //  8 KB

    if (nh > 0) {
        int z = blockIdx.z;
        int b = z / nh, h = z - b*nh;
        A += (long long)b*sAb + (long long)h*sAh;
        B += (long long)b*sBb + (long long)h*sBh;
        C += (long long)b*sCb + (long long)h*sCh;
    }
    int n0 = blockIdx.x * BN, m0 = blockIdx.y * BM;
    int tid = threadIdx.x;
    int warp = tid >> 5, lane = tid & 31;
    int wm = warp >> 2, wn = warp & 3;   // warps: 2 x 4 -> warp tile 64 x 32

    wmma::fragment<wmma::accumulator, 16, 16, 8, float> acc[4][2];
    #pragma unroll
    for (int i = 0; i < 4; i++)
        #pragma unroll
        for (int j = 0; j < 2; j++)
            wmma::fill_fragment(acc[i][j], 0.0f);

    int numK = (K + BK - 1) / BK;
    for (int kt = 0; kt < numK; kt++) {
        int kbase = kt * BK;
        #pragma unroll
        for (int i = 0; i < 16; i++) {                 // A: 128x32
            int idx = tid + i*256;
            int m = idx >> 5, k = idx & 31;
            int gm = m0 + m, gk = kbase + k;
            float v = 0.f;
            if (gm < M && gk < K) v = A[(size_t)gm*lda + gk];
            As[m][k] = wmma::__float_to_tf32(v);
        }
        #pragma unroll
        for (int i = 0; i < 16; i++) {                 // B: 32x128
            int idx = tid + i*256;
            int k = idx >> 7, n = idx & 127;
            int gk = kbase + k, gn = n0 + n;
            float v = 0.f;
            if (gk < K && gn < N)
                v = BT ? B[(size_t)gn*ldb + gk] : B[(size_t)gk*ldb + gn];
            Bs[k][n] = wmma::__float_to_tf32(v);
        }
        __syncthreads();

        #pragma unroll
        for (int kk = 0; kk < BK; kk += 8) {
            wmma::fragment<wmma::matrix_a, 16, 16, 8, wmma::precision::tf32, wmma::row_major> af[4];
            wmma::fragment<wmma::matrix_b, 16, 16, 8, wmma::precision::tf32, wmma::row_major> bf[2];
            #pragma unroll
            for (int i = 0; i < 4; i++)
                wmma::load_matrix_sync(af[i], &As[wm*64 + i*16][kk], BK);
            #pragma unroll
            for (int j = 0; j < 2; j++)
                wmma::load_matrix_sync(bf[j], &Bs[kk][wn*32 + j*16], BN);
            #pragma unroll
            for (int i = 0; i < 4; i++)
                #pragma unroll
                for (int j = 0; j < 2; j++)
                    wmma::mma_sync(acc[i][j], af[i], bf[j], acc[i][j]);
        }
        __syncthreads();
    }

    // epilogue: stage each 16x16 fragment through per-warp smem, guarded store
    #pragma unroll
    for (int i = 0; i < 4; i++) {
        #pragma unroll
        for (int j = 0; j < 2; j++) {
            wmma::store_matrix_sync(&stage[warp][0], acc[i][j], 16, wmma::mem_row_major);
            __syncwarp();
            int mb = m0 + wm*64 + i*16;
            int nb = n0 + wn*32 + j*16;
            #pragma unroll
            for (int e = lane; e < 256; e += 32) {
                int r = e >> 4, c = e & 15;
                int m = mb + r, n = nb + c;
                if (m < M && n < N) {
                    float v = stage[warp][e];
                    if (EPI == EPI_SCALE)      v *= scale;
                    else if (EPI == EPI_BIAS_RES) v = v + bias[n] + res[(size_t)m*ldr + n];
                    else if (EPI == EPI_BIAS_GELU) {
                        v += bias[n];
                        v = 0.5f * v * (1.0f + erff(v * 0.70710678118654752f));
                    }
                    C[(size_t)m*ldc + n] = v;
                }
            }
            __syncwarp();
        }
    }
}

// -------------------------------------------------------------------------------
extern "C" void kernel_launch(void* const* d_in, const int* in_sizes, int n_in,
                              void* d_out, int out_size)
{
    (void)in_sizes; (void)n_in; (void)out_size;
    const float* x      = (const float*)d_in[0];
    const float* mask   = (const float*)d_in[1];
    const float* qkv_w  = (const float*)d_in[2];
    const float* proj_w = (const float*)d_in[3];
    const float* proj_b = (const float*)d_in[4];
    const float* ln1_g  = (const float*)d_in[5];
    const float* ln1_b  = (const float*)d_in[6];
    const float* ln2_g  = (const float*)d_in[7];
    const float* ln2_b  = (const float*)d_in[8];
    const float* fc1_w  = (const float*)d_in[9];
    const float* fc1_b  = (const float*)d_in[10];
    const float* fc2_w  = (const float*)d_in[11];
    const float* fc2_b  = (const float*)d_in[12];
    float* out = (float*)d_out;

    float *xn, *qkv, *scor, *att, *x1, *h2, *hid;
    cudaGetSymbolAddress((void**)&xn,   g_xn);
    cudaGetSymbolAddress((void**)&qkv,  g_qkv);
    cudaGetSymbolAddress((void**)&scor, g_scor);
    cudaGetSymbolAddress((void**)&att,  g_att);
    cudaGetSymbolAddress((void**)&x1,   g_x1);
    cudaGetSymbolAddress((void**)&h2,   g_h2);
    cudaGetSymbolAddress((void**)&hid,  g_hid);

    const long long sQKVb = (long long)SEQ * 3*EMBED;  // per-batch stride in qkv
    const long long sSb   = (long long)NHEAD * SEQ * SEQ;
    const long long sSh   = (long long)SEQ * SEQ;

    // 1) LN1
    ln_kernel<<<ROWS, 256>>>(x, ln1_g, ln1_b, xn);

    // 2) QKV = xn @ qkv_w    [8992 x 3072]
    gemm_kernel<EPI_NONE, false><<<dim3(24, 71, 1), 256>>>(
        ROWS, 3*EMBED, EMBED,
        xn, EMBED, 0, 0,
        qkv_w, 3*EMBED, 0, 0,
        qkv, 3*EMBED, 0, 0,
        nullptr, nullptr, 0, 1.0f, 0);

    // 3) scores = Q @ K^T * 0.125   per (b,h)
    gemm_kernel<EPI_SCALE, true><<<dim3(9, 9, BATCH*NHEAD), 256>>>(
        SEQ, SEQ, HD,
        qkv,            3*EMBED, sQKVb, HD,      // Q: col offset 0, head h -> +64h
        qkv + EMBED,    3*EMBED, sQKVb, HD,      // K
        scor, SEQ, sSb, sSh,
        nullptr, nullptr, 0, 0.125f, NHEAD);

    // 4) masked softmax in place
    softmax_kernel<<<dim3(SEQ, NHEAD, BATCH), 128>>>(scor, mask);

    // 5) out_bh = attn @ V  -> att[b][s][h*64+d]
    gemm_kernel<EPI_NONE, false><<<dim3(1, 9, BATCH*NHEAD), 256>>>(
        SEQ, HD, SEQ,
        scor, SEQ, sSb, sSh,
        qkv + 2*EMBED, 3*EMBED, sQKVb, HD,       // V
        att, EMBED, (long long)SEQ*EMBED, HD,
        nullptr, nullptr, 0, 1.0f, NHEAD);

    // 6) x1 = att @ proj_w + proj_b + x
    gemm_kernel<EPI_BIAS_RES, false><<<dim3(8, 71, 1), 256>>>(
        ROWS, EMBED, EMBED,
        att, EMBED, 0, 0,
        proj_w, EMBED, 0, 0,
        x1, EMBED, 0, 0,
        proj_b, x, EMBED, 1.0f, 0);

    // 7) LN2
    ln_kernel<<<ROWS, 256>>>(x1, ln2_g, ln2_b, h2);

    // 8) hid = gelu(h2 @ fc1_w + fc1_b)
    gemm_kernel<EPI_BIAS_GELU, false><<<dim3(32, 71, 1), 256>>>(
        ROWS, MLPH, EMBED,
        h2, EMBED, 0, 0,
        fc1_w, MLPH, 0, 0,
        hid, MLPH, 0, 0,
        fc1_b, nullptr, 0, 1.0f, 0);

    // 9) out = hid @ fc2_w + fc2_b + x1
    gemm_kernel<EPI_BIAS_RES, false><<<dim3(8, 71, 1), 256>>>(
        ROWS, EMBED, MLPH,
        hid, MLPH, 0, 0,
        fc2_w, EMBED, 0, 0,
        out, EMBED, 0, 0,
        fc2_b, x1, EMBED, 1.0f, 0);
}

// round 4
// speedup vs baseline: 1.8508x; 1.8508x over previous
#include <cuda_runtime.h>
#include <cuda_bf16.h>
#include <mma.h>
#include <math.h>
#include <stdint.h>

using namespace nvcuda;

#define BATCH 8
#define SEQ   1124
#define EMBED 1024
#define NHEAD 16
#define HD    64
#define NQ    100
#define NP    1024
#define MLPH  4096
#define ROWS  (BATCH*SEQ)   // 8992

// ---------------- scratch (static device memory; no allocations allowed) ---------
__device__ float g_xn  [(size_t)ROWS*EMBED];
__device__ float g_qkv [(size_t)ROWS*3*EMBED];
__device__ float g_scor[(size_t)BATCH*NHEAD*SEQ*SEQ];
__device__ float g_att [(size_t)ROWS*EMBED];
__device__ float g_x1  [(size_t)ROWS*EMBED];
__device__ float g_h2  [(size_t)ROWS*EMBED];
__device__ float g_hid [(size_t)ROWS*MLPH];

// ---------------- cp.async helpers ----------------------------------------------
__device__ __forceinline__ void cp_async16(float* smem, const float* gmem, bool pred) {
    unsigned int s = (unsigned int)__cvta_generic_to_shared(smem);
    int sz = pred ? 16 : 0;
    asm volatile("cp.async.cg.shared.global [%0], [%1], 16, %2;\n"
                 :: "r"(s), "l"(gmem), "r"(sz));
}
__device__ __forceinline__ void cp_commit() {
    asm volatile("cp.async.commit_group;\n" ::: "memory");
}
template<int N>
__device__ __forceinline__ void cp_wait() {
    asm volatile("cp.async.wait_group %0;\n" :: "n"(N) : "memory");
}

// ---------------- LayerNorm over last dim (1024), one block per row -------------
__global__ void __launch_bounds__(256) ln_kernel(const float* __restrict__ x,
                                                 const float* __restrict__ g,
                                                 const float* __restrict__ b,
                                                 float* __restrict__ o)
{
    int row = blockIdx.x;
    const float4* xr = (const float4*)(x + (size_t)row*EMBED);
    float4 v = xr[threadIdx.x];
    float s  = v.x + v.y + v.z + v.w;
    float sq = v.x*v.x + v.y*v.y + v.z*v.z + v.w*v.w;

    __shared__ float red[2][8];
    #pragma unroll
    for (int off = 16; off > 0; off >>= 1) {
        s  += __shfl_down_sync(0xffffffffu, s,  off);
        sq += __shfl_down_sync(0xffffffffu, sq, off);
    }
    int w = threadIdx.x >> 5, l = threadIdx.x & 31;
    if (l == 0) { red[0][w] = s; red[1][w] = sq; }
    __syncthreads();
    if (threadIdx.x == 0) {
        float ts = 0.f, tq = 0.f;
        #pragma unroll
        for (int i = 0; i < 8; i++) { ts += red[0][i]; tq += red[1][i]; }
        red[0][0] = ts; red[1][0] = tq;
    }
    __syncthreads();
    float mean = red[0][0] * (1.0f/EMBED);
    float var  = red[1][0] * (1.0f/EMBED) - mean*mean;
    float inv  = rsqrtf(var + 1e-6f);

    int c = threadIdx.x * 4;
    float4 gv = *(const float4*)(g + c);
    float4 bv = *(const float4*)(b + c);
    float4 ov;
    ov.x = (v.x - mean) * inv * gv.x + bv.x;
    ov.y = (v.y - mean) * inv * gv.y + bv.y;
    ov.z = (v.z - mean) * inv * gv.z + bv.z;
    ov.w = (v.w - mean) * inv * gv.w + bv.w;
    ((float4*)(o + (size_t)row*EMBED))[threadIdx.x] = ov;
}

// ---------------- masked softmax over rows of length SEQ ------------------------
__global__ void __launch_bounds__(128) softmax_kernel(float* __restrict__ scores,
                                                      const float* __restrict__ mask)
{
    int q = blockIdx.x, h = blockIdx.y, b = blockIdx.z;
    float* row = scores + (((size_t)(b*NHEAD + h))*SEQ + q)*SEQ;
    const float* mrow = (q >= NP) ? (mask + ((size_t)b*NQ + (q - NP))*NP) : nullptr;

    float v[9];
    float mx = -3.0e38f;
    #pragma unroll
    for (int i = 0; i < 9; i++) {
        int c = threadIdx.x + i*128;
        float val = -3.0e38f;
        if (c < SEQ) {
            val = row[c];
            if (mrow && c < NP && !(mrow[c] > 0.5f)) val = -1e9f;
        }
        v[i] = val;
        mx = fmaxf(mx, val);
    }

    __shared__ float red[4];
    #pragma unroll
    for (int off = 16; off > 0; off >>= 1)
        mx = fmaxf(mx, __shfl_down_sync(0xffffffffu, mx, off));
    int w = threadIdx.x >> 5, l = threadIdx.x & 31;
    if (l == 0) red[w] = mx;
    __syncthreads();
    if (threadIdx.x == 0) {
        float m = red[0];
        #pragma unroll
        for (int i = 1; i < 4; i++) m = fmaxf(m, red[i]);
        red[0] = m;
    }
    __syncthreads();
    mx = red[0];
    __syncthreads();

    float s = 0.f;
    #pragma unroll
    for (int i = 0; i < 9; i++) {
        int c = threadIdx.x + i*128;
        if (c < SEQ) { v[i] = expf(v[i] - mx); s += v[i]; }
    }
    #pragma unroll
    for (int off = 16; off > 0; off >>= 1)
        s += __shfl_down_sync(0xffffffffu, s, off);
    if (l == 0) red[w] = s;
    __syncthreads();
    if (threadIdx.x == 0) {
        float t = 0.f;
        #pragma unroll
        for (int i = 0; i < 4; i++) t += red[i];
        red[0] = t;
    }
    __syncthreads();
    float inv = 1.0f / red[0];

    #pragma unroll
    for (int i = 0; i < 9; i++) {
        int c = threadIdx.x + i*128;
        if (c < SEQ) row[c] = v[i] * inv;
    }
}

// ---------------- TF32 WMMA GEMM, 3-stage cp.async pipeline ----------------------
// C[m,n] = sum_k A[m,k] * (BT ? B[n,k] : B[k,n]), batched by blockIdx.z=(b,h).
enum { EPI_NONE = 0, EPI_SCALE = 1, EPI_BIAS_RES = 2, EPI_BIAS_GELU = 3 };

template<int EPI, bool BT, int BN>
__global__ void __launch_bounds__(256) gemm_kernel(
    int M, int N, int K,
    const float* __restrict__ A, int lda, long long sAb, long long sAh,
    const float* __restrict__ B, int ldb, long long sBb, long long sBh,
    float* __restrict__ C, int ldc, long long sCb, long long sCh,
    const float* __restrict__ bias,
    const float* __restrict__ res, int ldr,
    float scale, int nh)
{
    constexpr int BM = 128, BK = 32, STAGES = 3;
    constexpr int AST = BK + 4;                    // padded strides
    constexpr int ASZ = BM * AST;
    constexpr int BST = BT ? (BK + 4) : (BN + 4);
    constexpr int BSZ = BT ? BN * (BK + 4) : BK * (BN + 4);
    constexpr int WN  = BN / 4;                    // warp tile n
    constexpr int NF  = WN / 16;                   // n fragments per warp

    extern __shared__ float smem[];
    float* Asm = smem;
    float* Bsm = smem + STAGES * ASZ;

    if (nh > 0) {
        int z = blockIdx.z;
        int b = z / nh, h = z - b*nh;
        A += (long long)b*sAb + (long long)h*sAh;
        B += (long long)b*sBb + (long long)h*sBh;
        C += (long long)b*sCb + (long long)h*sCh;
    }
    int n0 = blockIdx.x * BN, m0 = blockIdx.y * BM;
    int tid = threadIdx.x;
    int warp = tid >> 5, lane = tid & 31;
    int wm = warp >> 2, wn = warp & 3;   // 2 x 4 warps; warp tile 64 x WN

    wmma::fragment<wmma::accumulator, 16, 16, 8, float> acc[4][NF];
    #pragma unroll
    for (int i = 0; i < 4; i++)
        #pragma unroll
        for (int j = 0; j < NF; j++)
            wmma::fill_fragment(acc[i][j], 0.0f);

    int numK = (K + BK - 1) / BK;

    auto load_tile = [&](int kt, int stage) {
        if (kt < numK) {
            int kbase = kt * BK;
            float* As = Asm + stage * ASZ;
            float* Bs = Bsm + stage * BSZ;
            #pragma unroll
            for (int i = 0; i < (BM*BK/4)/256; i++) {       // A: float4 along k
                int idx = tid + i*256;
                int m = idx >> 3, k4 = (idx & 7) * 4;
                int gm = m0 + m, gk = kbase + k4;
                bool p = (gm < M) && (gk < K);
                cp_async16(As + m*AST + k4, A + (size_t)gm*lda + gk, p);
            }
            if (BT) {
                #pragma unroll
                for (int i = 0; i < (BN*BK/4)/256; i++) {   // B rows are n, contiguous k
                    int idx = tid + i*256;
                    int n = idx >> 3, k4 = (idx & 7) * 4;
                    int gn = n0 + n, gk = kbase + k4;
                    bool p = (gn < N) && (gk < K);
                    cp_async16(Bs + n*BST + k4, B + (size_t)gn*ldb + gk, p);
                }
            } else {
                constexpr int N4 = BN / 4;
                #pragma unroll
                for (int i = 0; i < (BK*BN/4)/256; i++) {   // B rows are k, contiguous n
                    int idx = tid + i*256;
                    int k = idx / N4, n4 = (idx % N4) * 4;
                    int gk = kbase + k, gn = n0 + n4;
                    bool p = (gk < K) && (gn < N);
                    cp_async16(Bs + k*BST + n4, B + (size_t)gk*ldb + gn, p);
                }
            }
        }
        cp_commit();
    };

    #pragma unroll
    for (int s = 0; s < STAGES-1; s++) load_tile(s, s);

    for (int kt = 0; kt < numK; kt++) {
        int rs = kt % STAGES;
        cp_wait<STAGES-2>();
        __syncthreads();
        load_tile(kt + STAGES - 1, (kt + STAGES - 1) % STAGES);

        float* As = Asm + rs * ASZ;
        float* Bs = Bsm + rs * BSZ;
        #pragma unroll
        for (int kk = 0; kk < BK; kk += 8) {
            wmma::fragment<wmma::matrix_a, 16, 16, 8, wmma::precision::tf32, wmma::row_major> af[4];
            #pragma unroll
            for (int i = 0; i < 4; i++) {
                wmma::load_matrix_sync(af[i], As + (wm*64 + i*16)*AST + kk, AST);
                #pragma unroll
                for (int t = 0; t < af[i].num_elements; t++)
                    af[i].x[t] = wmma::__float_to_tf32(af[i].x[t]);
            }
            if (BT) {
                wmma::fragment<wmma::matrix_b, 16, 16, 8, wmma::precision::tf32, wmma::col_major> bf[NF];
                #pragma unroll
                for (int j = 0; j < NF; j++) {
                    wmma::load_matrix_sync(bf[j], Bs + (wn*WN + j*16)*BST + kk, BST);
                    #pragma unroll
                    for (int t = 0; t < bf[j].num_elements; t++)
                        bf[j].x[t] = wmma::__float_to_tf32(bf[j].x[t]);
                }
                #pragma unroll
                for (int i = 0; i < 4; i++)
                    #pragma unroll
                    for (int j = 0; j < NF; j++)
                        wmma::mma_sync(acc[i][j], af[i], bf[j], acc[i][j]);
            } else {
                wmma::fragment<wmma::matrix_b, 16, 16, 8, wmma::precision::tf32, wmma::row_major> bf[NF];
                #pragma unroll
                for (int j = 0; j < NF; j++) {
                    wmma::load_matrix_sync(bf[j], Bs + kk*BST + wn*WN + j*16, BST);
                    #pragma unroll
                    for (int t = 0; t < bf[j].num_elements; t++)
                        bf[j].x[t] = wmma::__float_to_tf32(bf[j].x[t]);
                }
                #pragma unroll
                for (int i = 0; i < 4; i++)
                    #pragma unroll
                    for (int j = 0; j < NF; j++)
                        wmma::mma_sync(acc[i][j], af[i], bf[j], acc[i][j]);
            }
        }
    }

    // epilogue: stage each 16x16 fragment through per-warp smem, guarded store
    __syncthreads();
    float* stg = smem + warp * 256;
    #pragma unroll
    for (int i = 0; i < 4; i++) {
        #pragma unroll
        for (int j = 0; j < NF; j++) {
            wmma::store_matrix_sync(stg, acc[i][j], 16, wmma::mem_row_major);
            __syncwarp();
            int mb = m0 + wm*64 + i*16;
            int nb = n0 + wn*WN + j*16;
            #pragma unroll
            for (int e = lane; e < 256; e += 32) {
                int r = e >> 4, c = e & 15;
                int m = mb + r, n = nb + c;
                if (m < M && n < N) {
                    float v = stg[e];
                    if (EPI == EPI_SCALE)         v *= scale;
                    else if (EPI == EPI_BIAS_RES) v = v + bias[n] + res[(size_t)m*ldr + n];
                    else if (EPI == EPI_BIAS_GELU) {
                        v += bias[n];
                        v = 0.5f * v * (1.0f + erff(v * 0.70710678118654752f));
                    }
                    C[(size_t)m*ldc + n] = v;
                }
            }
            __syncwarp();
        }
    }
}

// smem sizes per instantiation (floats): STAGES*(ASZ+BSZ)
static int smem_bytes(bool bt, int bn) {
    int asz = 128 * 36;
    int bsz = bt ? bn * 36 : 32 * (bn + 4);
    return 3 * (asz + bsz) * 4;
}

// -------------------------------------------------------------------------------
extern "C" void kernel_launch(void* const* d_in, const int* in_sizes, int n_in,
                              void* d_out, int out_size)
{
    (void)in_sizes; (void)n_in; (void)out_size;
    const float* x      = (const float*)d_in[0];
    const float* mask   = (const float*)d_in[1];
    const float* qkv_w  = (const float*)d_in[2];
    const float* proj_w = (const float*)d_in[3];
    const float* proj_b = (const float*)d_in[4];
    const float* ln1_g  = (const float*)d_in[5];
    const float* ln1_b  = (const float*)d_in[6];
    const float* ln2_g  = (const float*)d_in[7];
    const float* ln2_b  = (const float*)d_in[8];
    const float* fc1_w  = (const float*)d_in[9];
    const float* fc1_b  = (const float*)d_in[10];
    const float* fc2_w  = (const float*)d_in[11];
    const float* fc2_b  = (const float*)d_in[12];
    float* out = (float*)d_out;

    float *xn, *qkv, *scor, *att, *x1, *h2, *hid;
    cudaGetSymbolAddress((void**)&xn,   g_xn);
    cudaGetSymbolAddress((void**)&qkv,  g_qkv);
    cudaGetSymbolAddress((void**)&scor, g_scor);
    cudaGetSymbolAddress((void**)&att,  g_att);
    cudaGetSymbolAddress((void**)&x1,   g_x1);
    cudaGetSymbolAddress((void**)&h2,   g_h2);
    cudaGetSymbolAddress((void**)&hid,  g_hid);

    // capture-safe (non-stream API, executes immediately); called every time —
    // no static guards allowed by the harness contract.
    cudaFuncSetAttribute(gemm_kernel<EPI_NONE, false, 128>,
        cudaFuncAttributeMaxDynamicSharedMemorySize, smem_bytes(false, 128));
    cudaFuncSetAttribute(gemm_kernel<EPI_SCALE, true, 128>,
        cudaFuncAttributeMaxDynamicSharedMemorySize, smem_bytes(true, 128));
    cudaFuncSetAttribute(gemm_kernel<EPI_NONE, false, 64>,
        cudaFuncAttributeMaxDynamicSharedMemorySize, smem_bytes(false, 64));
    cudaFuncSetAttribute(gemm_kernel<EPI_BIAS_RES, false, 128>,
        cudaFuncAttributeMaxDynamicSharedMemorySize, smem_bytes(false, 128));
    cudaFuncSetAttribute(gemm_kernel<EPI_BIAS_GELU, false, 128>,
        cudaFuncAttributeMaxDynamicSharedMemorySize, smem_bytes(false, 128));

    const long long sQKVb = (long long)SEQ * 3*EMBED;
    const long long sSb   = (long long)NHEAD * SEQ * SEQ;
    const long long sSh   = (long long)SEQ * SEQ;

    // 1) LN1
    ln_kernel<<<ROWS, 256>>>(x, ln1_g, ln1_b, xn);

    // 2) QKV = xn @ qkv_w    [8992 x 3072]
    gemm_kernel<EPI_NONE, false, 128><<<dim3(24, 71, 1), 256, smem_bytes(false,128)>>>(
        ROWS, 3*EMBED, EMBED,
        xn, EMBED, 0, 0,
        qkv_w, 3*EMBED, 0, 0,
        qkv, 3*EMBED, 0, 0,
        nullptr, nullptr, 0, 1.0f, 0);

    // 3) scores = Q @ K^T * 0.125   per (b,h)
    gemm_kernel<EPI_SCALE, true, 128><<<dim3(9, 9, BATCH*NHEAD), 256, smem_bytes(true,128)>>>(
        SEQ, SEQ, HD,
        qkv,            3*EMBED, sQKVb, HD,
        qkv + EMBED,    3*EMBED, sQKVb, HD,
        scor, SEQ, sSb, sSh,
        nullptr, nullptr, 0, 0.125f, NHEAD);

    // 4) masked softmax in place
    softmax_kernel<<<dim3(SEQ, NHEAD, BATCH), 128>>>(scor, mask);

    // 5) out_bh = attn @ V  -> att[b][s][h*64+d]
    gemm_kernel<EPI_NONE, false, 64><<<dim3(1, 9, BATCH*NHEAD), 256, smem_bytes(false,64)>>>(
        SEQ, HD, SEQ,
        scor, SEQ, sSb, sSh,
        qkv + 2*EMBED, 3*EMBED, sQKVb, HD,
        att, EMBED, (long long)SEQ*EMBED, HD,
        nullptr, nullptr, 0, 1.0f, NHEAD);

    // 6) x1 = att @ proj_w + proj_b + x
    gemm_kernel<EPI_BIAS_RES, false, 128><<<dim3(8, 71, 1), 256, smem_bytes(false,128)>>>(
        ROWS, EMBED, EMBED,
        att, EMBED, 0, 0,
        proj_w, EMBED, 0, 0,
        x1, EMBED, 0, 0,
        proj_b, x, EMBED, 1.0f, 0);

    // 7) LN2
    ln_kernel<<<ROWS, 256>>>(x1, ln2_g, ln2_b, h2);

    // 8) hid = gelu(h2 @ fc1_w + fc1_b)
    gemm_kernel<EPI_BIAS_GELU, false, 128><<<dim3(32, 71, 1), 256, smem_bytes(false,128)>>>(
        ROWS, MLPH, EMBED,
        h2, EMBED, 0, 0,
        fc1_w, MLPH, 0, 0,
        hid, MLPH, 0, 0,
        fc1_b, nullptr, 0, 1.0f, 0);

    // 9) out = hid @ fc2_w + fc2_b + x1
    gemm_kernel<EPI_BIAS_RES, false, 128><<<dim3(8, 71, 1), 256, smem_bytes(false,128)>>>(
        ROWS, EMBED, MLPH,
        hid, MLPH, 0, 0,
        fc2_w, EMBED, 0, 0,
        out, EMBED, 0, 0,
        fc2_b, x1, EMBED, 1.0f, 0);
}